// round 14
// baseline (speedup 1.0000x reference)
#include <cuda_runtime.h>
#include <cuda_bf16.h>
#include <math.h>

#define BATCH 4
#define SEQ   1024
#define DIM   1024
#define NH    16
#define DH    64
#define PAD   68

// packed-f32x2 helpers (attention)
#define DUP2(d, s)      asm("mov.b64 %0, {%1, %1};" : "=l"(d) : "f"(s))
#define FMA2(a, x, y)   asm("fma.rn.f32x2 %0, %1, %2, %0;" : "+l"(a) : "l"(x), "l"(y))
#define MUL2(a, x)      asm("mul.rn.f32x2 %0, %1, %2;" : "=l"(a) : "l"(a), "l"(x))
#define UNPK2(lo, hi, v) asm("mov.b64 {%0, %1}, %2;" : "=f"(lo), "=f"(hi) : "l"(v))

// Scratch (allocation-free)
__device__ float g_qkv[BATCH * SEQ * 3 * DIM];
__device__ float g_att[BATCH * SEQ * DIM];
__device__ __nv_bfloat16 g_xh[BATCH * SEQ * DIM];
__device__ __nv_bfloat16 g_xl[BATCH * SEQ * DIM];
__device__ __nv_bfloat16 g_wqh[3 * DIM * DIM];   // transposed [N][K]
__device__ __nv_bfloat16 g_wql[3 * DIM * DIM];
__device__ __nv_bfloat16 g_woh[DIM * DIM];       // transposed [N][K]
__device__ __nv_bfloat16 g_wol[DIM * DIM];
__device__ __nv_bfloat16 g_ath[BATCH * SEQ * DIM];
__device__ __nv_bfloat16 g_atl[BATCH * SEQ * DIM];

// ---------------------------------------------------------------------------
// Split fp32 -> (hi, lo) bf16 planes, elementwise (A-side matrices).
// ---------------------------------------------------------------------------
__global__ __launch_bounds__(256) void split_bf16(const float* __restrict__ in,
                                                  __nv_bfloat16* __restrict__ hi,
                                                  __nv_bfloat16* __restrict__ lo,
                                                  int n4) {
    int i = blockIdx.x * blockDim.x + threadIdx.x;
    if (i >= n4) return;
    float4 v = ((const float4*)in)[i];
    float vv[4] = {v.x, v.y, v.z, v.w};
    __nv_bfloat16 h[4], l[4];
#pragma unroll
    for (int e = 0; e < 4; e++) {
        h[e] = __float2bfloat16_rn(vv[e]);
        l[e] = __float2bfloat16_rn(vv[e] - __bfloat162float(h[e]));
    }
    *(uint2*)&hi[4 * i] = *(uint2*)h;
    *(uint2*)&lo[4 * i] = *(uint2*)l;
}

// ---------------------------------------------------------------------------
// Transpose-split: W[K][N] fp32 -> Th[N][K], Tl[N][K] bf16.
// 32x32 tiles via smem; block (32, 8).
// ---------------------------------------------------------------------------
__global__ __launch_bounds__(256) void split_wt(const float* __restrict__ W,
                                                __nv_bfloat16* __restrict__ Th,
                                                __nv_bfloat16* __restrict__ Tl,
                                                int K, int N) {
    __shared__ __nv_bfloat16 th[32][33];
    __shared__ __nv_bfloat16 tl[32][33];
    int n0 = blockIdx.x * 32, k0 = blockIdx.y * 32;
    int tx = threadIdx.x, ty = threadIdx.y;
#pragma unroll
    for (int i = 0; i < 4; i++) {
        int kl = ty + i * 8;
        float v = W[(size_t)(k0 + kl) * N + n0 + tx];
        __nv_bfloat16 h = __float2bfloat16_rn(v);
        th[kl][tx] = h;
        tl[kl][tx] = __float2bfloat16_rn(v - __bfloat162float(h));
    }
    __syncthreads();
#pragma unroll
    for (int i = 0; i < 4; i++) {
        int nl = ty + i * 8;
        Th[(size_t)(n0 + nl) * K + k0 + tx] = th[tx][nl];
        Tl[(size_t)(n0 + nl) * K + k0 + tx] = tl[tx][nl];
    }
}

// ---------------------------------------------------------------------------
// BF16 tensor-core GEMM, 3-term compensation (ah*bh + ah*bl + al*bh),
// mma.sync.m16n8k16, pre-split bf16 inputs (B transposed [N][K]),
// double-buffered cp.async. Block 128x128x32, 256 thr / 8 warps (2x4),
// warp tile 64x32.
// ---------------------------------------------------------------------------
#define SAS 40                          // bf16 stride, conflict-free (80B)
#define A_ELEMS (128 * SAS)             // per plane
#define STAGE_ELEMS (4 * A_ELEMS)       // Ah, Al, Bh, Bl
#define GEMM_SMEM (2 * STAGE_ELEMS * (int)sizeof(__nv_bfloat16))  // 81920

#define MMA_BF16(D, A, B)                                                    \
    asm("mma.sync.aligned.m16n8k16.row.col.f32.bf16.bf16.f32 "              \
        "{%0,%1,%2,%3}, {%4,%5,%6,%7}, {%8,%9}, {%0,%1,%2,%3};"             \
        : "+f"(D[0]), "+f"(D[1]), "+f"(D[2]), "+f"(D[3])                     \
        : "r"(A[0]), "r"(A[1]), "r"(A[2]), "r"(A[3]), "r"(B[0]), "r"(B[1]))

__device__ __forceinline__ void cpa16b(__nv_bfloat16* dst, const __nv_bfloat16* src) {
    unsigned u = (unsigned)__cvta_generic_to_shared(dst);
    asm volatile("cp.async.cg.shared.global [%0], [%1], 16;" :: "r"(u), "l"(src));
}

__device__ __forceinline__ void fill_stage(__nv_bfloat16* buf,
                                           const __nv_bfloat16* __restrict__ Ah,
                                           const __nv_bfloat16* __restrict__ Al,
                                           const __nv_bfloat16* __restrict__ Bh,
                                           const __nv_bfloat16* __restrict__ Bl,
                                           int row0, int col0, int k0,
                                           int K, int tid) {
    __nv_bfloat16* sAh = buf;
    __nv_bfloat16* sAl = buf + A_ELEMS;
    __nv_bfloat16* sBh = buf + 2 * A_ELEMS;
    __nv_bfloat16* sBl = buf + 3 * A_ELEMS;
#pragma unroll
    for (int v = 0; v < 2; v++) {
        int idx = tid + v * 256;          // 0..511
        int r   = idx >> 2;               // 0..127
        int c8  = (idx & 3) << 3;         // 0,8,16,24
        size_t ga = (size_t)(row0 + r) * K + k0 + c8;   // A[m][k]
        cpa16b(sAh + r * SAS + c8, Ah + ga);
        cpa16b(sAl + r * SAS + c8, Al + ga);
        size_t gb = (size_t)(col0 + r) * K + k0 + c8;   // Bt[n][k]
        cpa16b(sBh + r * SAS + c8, Bh + gb);
        cpa16b(sBl + r * SAS + c8, Bl + gb);
    }
}

__global__ __launch_bounds__(256) void bf16gemm(const __nv_bfloat16* __restrict__ Ah,
                                                const __nv_bfloat16* __restrict__ Al,
                                                const __nv_bfloat16* __restrict__ Bh,
                                                const __nv_bfloat16* __restrict__ Bl,
                                                float* __restrict__ C,
                                                int M, int N, int K) {
    extern __shared__ __nv_bfloat16 smem[];

    const int tid  = threadIdx.x;
    const int row0 = blockIdx.y * 128;
    const int col0 = blockIdx.x * 128;

    const int lane = tid & 31;
    const int wid  = tid >> 5;
    const int wm   = (wid >> 2) * 64;
    const int wn   = (wid & 3) * 32;
    const int g    = lane >> 2;
    const int tg   = lane & 3;

    float acc[4][4][4];
#pragma unroll
    for (int mt = 0; mt < 4; mt++)
#pragma unroll
        for (int nt = 0; nt < 4; nt++)
#pragma unroll
            for (int r = 0; r < 4; r++) acc[mt][nt][r] = 0.0f;

    const int NIT = K / 32;

    fill_stage(smem, Ah, Al, Bh, Bl, row0, col0, 0, K, tid);
    asm volatile("cp.async.commit_group;");

    for (int it = 0; it < NIT; it++) {
        __nv_bfloat16* cur = smem + (it & 1) * STAGE_ELEMS;
        if (it + 1 < NIT) {
            fill_stage(smem + ((it + 1) & 1) * STAGE_ELEMS,
                       Ah, Al, Bh, Bl, row0, col0, (it + 1) * 32, K, tid);
            asm volatile("cp.async.commit_group;");
            asm volatile("cp.async.wait_group 1;");
        } else {
            asm volatile("cp.async.wait_group 0;");
        }
        __syncthreads();

        __nv_bfloat16* sAh = cur;
        __nv_bfloat16* sAl = cur + A_ELEMS;
        __nv_bfloat16* sBh = cur + 2 * A_ELEMS;
        __nv_bfloat16* sBl = cur + 3 * A_ELEMS;

#pragma unroll
        for (int ks = 0; ks < 2; ks++) {
            const int k = ks * 16;
            unsigned bh[4][2], bl[4][2];
#pragma unroll
            for (int nt = 0; nt < 4; nt++) {
                int nrow = wn + nt * 8 + g;
                bh[nt][0] = *(const unsigned*)&sBh[nrow * SAS + k + 2 * tg];
                bh[nt][1] = *(const unsigned*)&sBh[nrow * SAS + k + 2 * tg + 8];
                bl[nt][0] = *(const unsigned*)&sBl[nrow * SAS + k + 2 * tg];
                bl[nt][1] = *(const unsigned*)&sBl[nrow * SAS + k + 2 * tg + 8];
            }
#pragma unroll
            for (int mt = 0; mt < 4; mt++) {
                int r = wm + mt * 16 + g;
                unsigned ah[4], al[4];
                ah[0] = *(const unsigned*)&sAh[r * SAS + k + 2 * tg];
                ah[1] = *(const unsigned*)&sAh[(r + 8) * SAS + k + 2 * tg];
                ah[2] = *(const unsigned*)&sAh[r * SAS + k + 2 * tg + 8];
                ah[3] = *(const unsigned*)&sAh[(r + 8) * SAS + k + 2 * tg + 8];
                al[0] = *(const unsigned*)&sAl[r * SAS + k + 2 * tg];
                al[1] = *(const unsigned*)&sAl[(r + 8) * SAS + k + 2 * tg];
                al[2] = *(const unsigned*)&sAl[r * SAS + k + 2 * tg + 8];
                al[3] = *(const unsigned*)&sAl[(r + 8) * SAS + k + 2 * tg + 8];
#pragma unroll
                for (int nt = 0; nt < 4; nt++) {
                    MMA_BF16(acc[mt][nt], ah, bh[nt]);
                    MMA_BF16(acc[mt][nt], ah, bl[nt]);
                    MMA_BF16(acc[mt][nt], al, bh[nt]);
                }
            }
        }
        __syncthreads();
    }

#pragma unroll
    for (int mt = 0; mt < 4; mt++)
#pragma unroll
        for (int nt = 0; nt < 4; nt++) {
            int r = row0 + wm + mt * 16 + g;
            int c = col0 + wn + nt * 8 + tg * 2;
            *(float2*)&C[(size_t)r * N + c]       = make_float2(acc[mt][nt][0], acc[mt][nt][1]);
            *(float2*)&C[(size_t)(r + 8) * N + c] = make_float2(acc[mt][nt][2], acc[mt][nt][3]);
        }
}

// ---------------------------------------------------------------------------
// RoPE — interleaved pairs, rotation by -theta (verified R6).
// ---------------------------------------------------------------------------
__global__ void rope_kernel(float* __restrict__ qkv) {
    int idx = blockIdx.x * blockDim.x + threadIdx.x;
    int i = idx & 15;
    int h = (idx >> 4) & 15;
    int s = (idx >> 8) & 1;
    int t = (idx >> 9) & 1023;
    int b = idx >> 19;

    float inv_freq = powf(10000.0f, -(float)(2 * i) / 32.0f);
    float ang = (float)t * inv_freq;
    float c, sn;
    sincosf(ang, &c, &sn);

    size_t base = ((size_t)(b * SEQ + t)) * (3 * DIM) + s * DIM + h * DH + 2 * i;
    float v0 = qkv[base], v1 = qkv[base + 1];
    qkv[base]     = v0 * c + v1 * sn;
    qkv[base + 1] = v1 * c - v0 * sn;
}

// ---------------------------------------------------------------------------
// Flash attention (causal), fp32, f32x2-packed inner products (unchanged).
// ---------------------------------------------------------------------------
__global__ __launch_bounds__(256) void attn_kernel(const float* __restrict__ qkv,
                                                   float* __restrict__ out) {
    extern __shared__ float sm[];
    float* Qs = sm;
    float* Kt = Qs + 64 * PAD;
    float* Vs = Kt + 64 * PAD;
    float* Ps = Vs + 64 * PAD;

    const int qt = blockIdx.x;
    const int h  = blockIdx.y;
    const int b  = blockIdx.z;
    const int tid = threadIdx.x;
    const int ty = tid >> 4, tx = tid & 15;
    const int lr = tid >> 4, lc4 = (tid & 15) << 2;

    const float* qb = qkv + ((size_t)(b * SEQ + qt * 64)) * (3 * DIM) + h * DH;
#pragma unroll
    for (int rr = 0; rr < 4; rr++) {
        int row = rr * 16 + lr;
        float4 v = *(const float4*)(qb + (size_t)row * (3 * DIM) + lc4);
        Qs[row * PAD + lc4 + 0] = v.x;
        Qs[row * PAD + lc4 + 1] = v.y;
        Qs[row * PAD + lc4 + 2] = v.z;
        Qs[row * PAD + lc4 + 3] = v.w;
    }

    float m_[4], l_[4];
    unsigned long long accp[4][2];
#pragma unroll
    for (int i = 0; i < 4; i++) {
        m_[i] = -INFINITY;
        l_[i] = 0.0f;
        accp[i][0] = 0ull;
        accp[i][1] = 0ull;
    }

    const float scale = 0.125f;

    for (int kt = 0; kt <= qt; kt++) {
        __syncthreads();

        const float* kb = qkv + ((size_t)(b * SEQ + kt * 64)) * (3 * DIM) + DIM + h * DH;
        const float* vb = kb + DIM;
#pragma unroll
        for (int rr = 0; rr < 4; rr++) {
            int row = rr * 16 + lr;
            float4 kv = *(const float4*)(kb + (size_t)row * (3 * DIM) + lc4);
            Kt[(lc4 + 0) * PAD + row] = kv.x;
            Kt[(lc4 + 1) * PAD + row] = kv.y;
            Kt[(lc4 + 2) * PAD + row] = kv.z;
            Kt[(lc4 + 3) * PAD + row] = kv.w;
            float4 vv = *(const float4*)(vb + (size_t)row * (3 * DIM) + lc4);
            Vs[row * PAD + lc4 + 0] = vv.x;
            Vs[row * PAD + lc4 + 1] = vv.y;
            Vs[row * PAD + lc4 + 2] = vv.z;
            Vs[row * PAD + lc4 + 3] = vv.w;
        }
        __syncthreads();

        unsigned long long s2[4][2];
#pragma unroll
        for (int i = 0; i < 4; i++) { s2[i][0] = 0ull; s2[i][1] = 0ull; }

#pragma unroll 8
        for (int d = 0; d < 64; d++) {
            unsigned long long kp0 = *(const unsigned long long*)&Kt[d * PAD + (tx << 2)];
            unsigned long long kp1 = *(const unsigned long long*)&Kt[d * PAD + (tx << 2) + 2];
#pragma unroll
            for (int i = 0; i < 4; i++) {
                unsigned long long qd;
                DUP2(qd, Qs[(ty * 4 + i) * PAD + d]);
                FMA2(s2[i][0], qd, kp0);
                FMA2(s2[i][1], qd, kp1);
            }
        }

        float s_[4][4];
#pragma unroll
        for (int i = 0; i < 4; i++) {
            UNPK2(s_[i][0], s_[i][1], s2[i][0]);
            UNPK2(s_[i][2], s_[i][3], s2[i][1]);
        }

#pragma unroll
        for (int i = 0; i < 4; i++) {
            float mx = -INFINITY;
#pragma unroll
            for (int j = 0; j < 4; j++) {
                float sv = s_[i][j] * scale;
                if (kt == qt && ((tx << 2) + j) > (ty * 4 + i)) sv = -INFINITY;
                s_[i][j] = sv;
                mx = fmaxf(mx, sv);
            }
#pragma unroll
            for (int off = 8; off > 0; off >>= 1)
                mx = fmaxf(mx, __shfl_xor_sync(0xffffffffu, mx, off));
            float mn  = fmaxf(m_[i], mx);
            float fac = expf(m_[i] - mn);
            float ps  = 0.0f;
#pragma unroll
            for (int j = 0; j < 4; j++) {
                float p = expf(s_[i][j] - mn);
                s_[i][j] = p;
                ps += p;
            }
#pragma unroll
            for (int off = 8; off > 0; off >>= 1)
                ps += __shfl_xor_sync(0xffffffffu, ps, off);
            m_[i] = mn;
            l_[i] = l_[i] * fac + ps;
            unsigned long long fd;
            DUP2(fd, fac);
            MUL2(accp[i][0], fd);
            MUL2(accp[i][1], fd);
        }

#pragma unroll
        for (int i = 0; i < 4; i++)
#pragma unroll
            for (int j = 0; j < 4; j++)
                Ps[(ty * 4 + i) * PAD + (tx << 2) + j] = s_[i][j];
        __syncthreads();

#pragma unroll 4
        for (int k = 0; k < 64; k++) {
            unsigned long long vp0 = *(const unsigned long long*)&Vs[k * PAD + (tx << 2)];
            unsigned long long vp1 = *(const unsigned long long*)&Vs[k * PAD + (tx << 2) + 2];
#pragma unroll
            for (int i = 0; i < 4; i++) {
                unsigned long long pd;
                DUP2(pd, Ps[(ty * 4 + i) * PAD + k]);
                FMA2(accp[i][0], pd, vp0);
                FMA2(accp[i][1], pd, vp1);
            }
        }
    }

#pragma unroll
    for (int i = 0; i < 4; i++) {
        float inv = 1.0f / l_[i];
        float o0, o1, o2, o3;
        UNPK2(o0, o1, accp[i][0]);
        UNPK2(o2, o3, accp[i][1]);
        int grow = b * SEQ + qt * 64 + ty * 4 + i;
        float4 o = make_float4(o0 * inv, o1 * inv, o2 * inv, o3 * inv);
        *(float4*)&out[(size_t)grow * DIM + h * DH + (tx << 2)] = o;
    }
}

// ---------------------------------------------------------------------------
extern "C" void kernel_launch(void* const* d_in, const int* in_sizes, int n_in,
                              void* d_out, int out_size) {
    const float* x    = nullptr;
    const float* Wqkv = nullptr;
    const float* Wout = nullptr;
    for (int i = 0; i < n_in; i++) {
        if (in_sizes[i] == BATCH * SEQ * DIM)  x    = (const float*)d_in[i];
        else if (in_sizes[i] == 3 * DIM * DIM) Wqkv = (const float*)d_in[i];
        else if (in_sizes[i] == DIM * DIM)     Wout = (const float*)d_in[i];
    }
    float* out = (float*)d_out;

    float *qkv, *att;
    __nv_bfloat16 *xh, *xl, *wqh, *wql, *woh, *wol, *ath, *atl;
    cudaGetSymbolAddress((void**)&qkv, g_qkv);
    cudaGetSymbolAddress((void**)&att, g_att);
    cudaGetSymbolAddress((void**)&xh,  g_xh);
    cudaGetSymbolAddress((void**)&xl,  g_xl);
    cudaGetSymbolAddress((void**)&wqh, g_wqh);
    cudaGetSymbolAddress((void**)&wql, g_wql);
    cudaGetSymbolAddress((void**)&woh, g_woh);
    cudaGetSymbolAddress((void**)&wol, g_wol);
    cudaGetSymbolAddress((void**)&ath, g_ath);
    cudaGetSymbolAddress((void**)&atl, g_atl);

    const int M = BATCH * SEQ;  // 4096

    cudaFuncSetAttribute(bf16gemm, cudaFuncAttributeMaxDynamicSharedMemorySize, GEMM_SMEM);

    // 0) Pre-split inputs to bf16 hi/lo planes (weights transposed)
    split_bf16<<<(M * DIM / 4) / 256, 256>>>(x, xh, xl, M * DIM / 4);
    split_wt<<<dim3(3 * DIM / 32, DIM / 32), dim3(32, 8)>>>(Wqkv, wqh, wql, DIM, 3 * DIM);
    split_wt<<<dim3(DIM / 32, DIM / 32), dim3(32, 8)>>>(Wout, woh, wol, DIM, DIM);

    // 1) QKV projection
    bf16gemm<<<dim3(3 * DIM / 128, M / 128), 256, GEMM_SMEM>>>(xh, xl, wqh, wql, qkv, M, 3 * DIM, DIM);

    // 2) RoPE (interleaved, -theta)
    rope_kernel<<<(BATCH * SEQ * 2 * NH * 16) / 256, 256>>>(qkv);

    // 3) Causal flash attention -> att
    int smem = 4 * 64 * PAD * (int)sizeof(float);
    cudaFuncSetAttribute(attn_kernel, cudaFuncAttributeMaxDynamicSharedMemorySize, smem);
    attn_kernel<<<dim3(SEQ / 64, NH, BATCH), 256, smem>>>(qkv, att);

    // 3b) Split attention output
    split_bf16<<<(M * DIM / 4) / 256, 256>>>(att, ath, atl, M * DIM / 4);

    // 4) Output projection
    bf16gemm<<<dim3(DIM / 128, M / 128), 256, GEMM_SMEM>>>(ath, atl, woh, wol, out, M, DIM, DIM);
}

// round 15
// speedup vs baseline: 1.0090x; 1.0090x over previous
#include <cuda_runtime.h>
#include <cuda_bf16.h>
#include <math.h>

#define BATCH 4
#define SEQ   1024
#define DIM   1024
#define NH    16
#define DH    64
#define PAD   68

// packed-f32x2 helpers (attention)
#define DUP2(d, s)      asm("mov.b64 %0, {%1, %1};" : "=l"(d) : "f"(s))
#define FMA2(a, x, y)   asm("fma.rn.f32x2 %0, %1, %2, %0;" : "+l"(a) : "l"(x), "l"(y))
#define MUL2(a, x)      asm("mul.rn.f32x2 %0, %1, %2;" : "=l"(a) : "l"(a), "l"(x))
#define UNPK2(lo, hi, v) asm("mov.b64 {%0, %1}, %2;" : "=f"(lo), "=f"(hi) : "l"(v))

// Scratch (allocation-free)
__device__ float g_qkv[BATCH * SEQ * 3 * DIM];
__device__ float g_att[BATCH * SEQ * DIM];
__device__ __nv_bfloat16 g_xh[BATCH * SEQ * DIM];
__device__ __nv_bfloat16 g_xl[BATCH * SEQ * DIM];
__device__ __nv_bfloat16 g_wqh[3 * DIM * DIM];   // transposed [N][K]
__device__ __nv_bfloat16 g_wql[3 * DIM * DIM];
__device__ __nv_bfloat16 g_woh[DIM * DIM];       // transposed [N][K]
__device__ __nv_bfloat16 g_wol[DIM * DIM];
__device__ __nv_bfloat16 g_ath[BATCH * SEQ * DIM];
__device__ __nv_bfloat16 g_atl[BATCH * SEQ * DIM];

// ---------------------------------------------------------------------------
// Split fp32 -> (hi, lo) bf16 planes, elementwise (A-side matrices).
// ---------------------------------------------------------------------------
__global__ __launch_bounds__(256) void split_bf16(const float* __restrict__ in,
                                                  __nv_bfloat16* __restrict__ hi,
                                                  __nv_bfloat16* __restrict__ lo,
                                                  int n4) {
    int i = blockIdx.x * blockDim.x + threadIdx.x;
    if (i >= n4) return;
    float4 v = ((const float4*)in)[i];
    float vv[4] = {v.x, v.y, v.z, v.w};
    __nv_bfloat16 h[4], l[4];
#pragma unroll
    for (int e = 0; e < 4; e++) {
        h[e] = __float2bfloat16_rn(vv[e]);
        l[e] = __float2bfloat16_rn(vv[e] - __bfloat162float(h[e]));
    }
    *(uint2*)&hi[4 * i] = *(uint2*)h;
    *(uint2*)&lo[4 * i] = *(uint2*)l;
}

// ---------------------------------------------------------------------------
// Transpose-split: W[K][N] fp32 -> Th[N][K], Tl[N][K] bf16.
// 32x32 tiles via smem; block (32, 8).
// ---------------------------------------------------------------------------
__global__ __launch_bounds__(256) void split_wt(const float* __restrict__ W,
                                                __nv_bfloat16* __restrict__ Th,
                                                __nv_bfloat16* __restrict__ Tl,
                                                int K, int N) {
    __shared__ __nv_bfloat16 th[32][33];
    __shared__ __nv_bfloat16 tl[32][33];
    int n0 = blockIdx.x * 32, k0 = blockIdx.y * 32;
    int tx = threadIdx.x, ty = threadIdx.y;
#pragma unroll
    for (int i = 0; i < 4; i++) {
        int kl = ty + i * 8;
        float v = W[(size_t)(k0 + kl) * N + n0 + tx];
        __nv_bfloat16 h = __float2bfloat16_rn(v);
        th[kl][tx] = h;
        tl[kl][tx] = __float2bfloat16_rn(v - __bfloat162float(h));
    }
    __syncthreads();
#pragma unroll
    for (int i = 0; i < 4; i++) {
        int nl = ty + i * 8;
        Th[(size_t)(n0 + nl) * K + k0 + tx] = th[tx][nl];
        Tl[(size_t)(n0 + nl) * K + k0 + tx] = tl[tx][nl];
    }
}

// ---------------------------------------------------------------------------
// BF16 tensor-core GEMM, 3-term compensation (ah*bh + ah*bl + al*bh),
// mma.sync.m16n8k16, pre-split bf16 inputs (B transposed [N][K]),
// double-buffered cp.async. Block 128x128x32, 256 thr / 8 warps (2x4),
// warp tile 64x32.
// ---------------------------------------------------------------------------
#define SAS 40                          // bf16 stride, conflict-free (80B)
#define A_ELEMS (128 * SAS)             // per plane
#define STAGE_ELEMS (4 * A_ELEMS)       // Ah, Al, Bh, Bl
#define GEMM_SMEM (2 * STAGE_ELEMS * (int)sizeof(__nv_bfloat16))  // 81920

#define MMA_BF16(D, A, B)                                                    \
    asm("mma.sync.aligned.m16n8k16.row.col.f32.bf16.bf16.f32 "              \
        "{%0,%1,%2,%3}, {%4,%5,%6,%7}, {%8,%9}, {%0,%1,%2,%3};"             \
        : "+f"(D[0]), "+f"(D[1]), "+f"(D[2]), "+f"(D[3])                     \
        : "r"(A[0]), "r"(A[1]), "r"(A[2]), "r"(A[3]), "r"(B[0]), "r"(B[1]))

__device__ __forceinline__ void cpa16b(__nv_bfloat16* dst, const __nv_bfloat16* src) {
    unsigned u = (unsigned)__cvta_generic_to_shared(dst);
    asm volatile("cp.async.cg.shared.global [%0], [%1], 16;" :: "r"(u), "l"(src));
}

__device__ __forceinline__ void fill_stage(__nv_bfloat16* buf,
                                           const __nv_bfloat16* __restrict__ Ah,
                                           const __nv_bfloat16* __restrict__ Al,
                                           const __nv_bfloat16* __restrict__ Bh,
                                           const __nv_bfloat16* __restrict__ Bl,
                                           int row0, int col0, int k0,
                                           int K, int tid) {
    __nv_bfloat16* sAh = buf;
    __nv_bfloat16* sAl = buf + A_ELEMS;
    __nv_bfloat16* sBh = buf + 2 * A_ELEMS;
    __nv_bfloat16* sBl = buf + 3 * A_ELEMS;
#pragma unroll
    for (int v = 0; v < 2; v++) {
        int idx = tid + v * 256;          // 0..511
        int r   = idx >> 2;               // 0..127
        int c8  = (idx & 3) << 3;         // 0,8,16,24
        size_t ga = (size_t)(row0 + r) * K + k0 + c8;   // A[m][k]
        cpa16b(sAh + r * SAS + c8, Ah + ga);
        cpa16b(sAl + r * SAS + c8, Al + ga);
        size_t gb = (size_t)(col0 + r) * K + k0 + c8;   // Bt[n][k]
        cpa16b(sBh + r * SAS + c8, Bh + gb);
        cpa16b(sBl + r * SAS + c8, Bl + gb);
    }
}

__global__ __launch_bounds__(256) void bf16gemm(const __nv_bfloat16* __restrict__ Ah,
                                                const __nv_bfloat16* __restrict__ Al,
                                                const __nv_bfloat16* __restrict__ Bh,
                                                const __nv_bfloat16* __restrict__ Bl,
                                                float* __restrict__ C,
                                                int M, int N, int K) {
    extern __shared__ __nv_bfloat16 smem[];

    const int tid  = threadIdx.x;
    const int row0 = blockIdx.y * 128;
    const int col0 = blockIdx.x * 128;

    const int lane = tid & 31;
    const int wid  = tid >> 5;
    const int wm   = (wid >> 2) * 64;
    const int wn   = (wid & 3) * 32;
    const int g    = lane >> 2;
    const int tg   = lane & 3;

    float acc[4][4][4];
#pragma unroll
    for (int mt = 0; mt < 4; mt++)
#pragma unroll
        for (int nt = 0; nt < 4; nt++)
#pragma unroll
            for (int r = 0; r < 4; r++) acc[mt][nt][r] = 0.0f;

    const int NIT = K / 32;

    fill_stage(smem, Ah, Al, Bh, Bl, row0, col0, 0, K, tid);
    asm volatile("cp.async.commit_group;");

    for (int it = 0; it < NIT; it++) {
        __nv_bfloat16* cur = smem + (it & 1) * STAGE_ELEMS;
        if (it + 1 < NIT) {
            fill_stage(smem + ((it + 1) & 1) * STAGE_ELEMS,
                       Ah, Al, Bh, Bl, row0, col0, (it + 1) * 32, K, tid);
            asm volatile("cp.async.commit_group;");
            asm volatile("cp.async.wait_group 1;");
        } else {
            asm volatile("cp.async.wait_group 0;");
        }
        __syncthreads();

        __nv_bfloat16* sAh = cur;
        __nv_bfloat16* sAl = cur + A_ELEMS;
        __nv_bfloat16* sBh = cur + 2 * A_ELEMS;
        __nv_bfloat16* sBl = cur + 3 * A_ELEMS;

#pragma unroll
        for (int ks = 0; ks < 2; ks++) {
            const int k = ks * 16;
            unsigned bh[4][2], bl[4][2];
#pragma unroll
            for (int nt = 0; nt < 4; nt++) {
                int nrow = wn + nt * 8 + g;
                bh[nt][0] = *(const unsigned*)&sBh[nrow * SAS + k + 2 * tg];
                bh[nt][1] = *(const unsigned*)&sBh[nrow * SAS + k + 2 * tg + 8];
                bl[nt][0] = *(const unsigned*)&sBl[nrow * SAS + k + 2 * tg];
                bl[nt][1] = *(const unsigned*)&sBl[nrow * SAS + k + 2 * tg + 8];
            }
#pragma unroll
            for (int mt = 0; mt < 4; mt++) {
                int r = wm + mt * 16 + g;
                unsigned ah[4], al[4];
                ah[0] = *(const unsigned*)&sAh[r * SAS + k + 2 * tg];
                ah[1] = *(const unsigned*)&sAh[(r + 8) * SAS + k + 2 * tg];
                ah[2] = *(const unsigned*)&sAh[r * SAS + k + 2 * tg + 8];
                ah[3] = *(const unsigned*)&sAh[(r + 8) * SAS + k + 2 * tg + 8];
                al[0] = *(const unsigned*)&sAl[r * SAS + k + 2 * tg];
                al[1] = *(const unsigned*)&sAl[(r + 8) * SAS + k + 2 * tg];
                al[2] = *(const unsigned*)&sAl[r * SAS + k + 2 * tg + 8];
                al[3] = *(const unsigned*)&sAl[(r + 8) * SAS + k + 2 * tg + 8];
#pragma unroll
                for (int nt = 0; nt < 4; nt++) {
                    MMA_BF16(acc[mt][nt], ah, bh[nt]);
                    MMA_BF16(acc[mt][nt], ah, bl[nt]);
                    MMA_BF16(acc[mt][nt], al, bh[nt]);
                }
            }
        }
        __syncthreads();
    }

#pragma unroll
    for (int mt = 0; mt < 4; mt++)
#pragma unroll
        for (int nt = 0; nt < 4; nt++) {
            int r = row0 + wm + mt * 16 + g;
            int c = col0 + wn + nt * 8 + tg * 2;
            *(float2*)&C[(size_t)r * N + c]       = make_float2(acc[mt][nt][0], acc[mt][nt][1]);
            *(float2*)&C[(size_t)(r + 8) * N + c] = make_float2(acc[mt][nt][2], acc[mt][nt][3]);
        }
}

// ---------------------------------------------------------------------------
// RoPE — interleaved pairs, rotation by -theta (verified R6).
// ---------------------------------------------------------------------------
__global__ void rope_kernel(float* __restrict__ qkv) {
    int idx = blockIdx.x * blockDim.x + threadIdx.x;
    int i = idx & 15;
    int h = (idx >> 4) & 15;
    int s = (idx >> 8) & 1;
    int t = (idx >> 9) & 1023;
    int b = idx >> 19;

    float inv_freq = powf(10000.0f, -(float)(2 * i) / 32.0f);
    float ang = (float)t * inv_freq;
    float c, sn;
    sincosf(ang, &c, &sn);

    size_t base = ((size_t)(b * SEQ + t)) * (3 * DIM) + s * DIM + h * DH + 2 * i;
    float v0 = qkv[base], v1 = qkv[base + 1];
    qkv[base]     = v0 * c + v1 * sn;
    qkv[base + 1] = v1 * c - v0 * sn;
}

// ---------------------------------------------------------------------------
// Flash attention (causal), fp32, f32x2-packed inner products (unchanged).
// ---------------------------------------------------------------------------
__global__ __launch_bounds__(256) void attn_kernel(const float* __restrict__ qkv,
                                                   float* __restrict__ out) {
    extern __shared__ float sm[];
    float* Qs = sm;
    float* Kt = Qs + 64 * PAD;
    float* Vs = Kt + 64 * PAD;
    float* Ps = Vs + 64 * PAD;

    const int qt = blockIdx.x;
    const int h  = blockIdx.y;
    const int b  = blockIdx.z;
    const int tid = threadIdx.x;
    const int ty = tid >> 4, tx = tid & 15;
    const int lr = tid >> 4, lc4 = (tid & 15) << 2;

    const float* qb = qkv + ((size_t)(b * SEQ + qt * 64)) * (3 * DIM) + h * DH;
#pragma unroll
    for (int rr = 0; rr < 4; rr++) {
        int row = rr * 16 + lr;
        float4 v = *(const float4*)(qb + (size_t)row * (3 * DIM) + lc4);
        Qs[row * PAD + lc4 + 0] = v.x;
        Qs[row * PAD + lc4 + 1] = v.y;
        Qs[row * PAD + lc4 + 2] = v.z;
        Qs[row * PAD + lc4 + 3] = v.w;
    }

    float m_[4], l_[4];
    unsigned long long accp[4][2];
#pragma unroll
    for (int i = 0; i < 4; i++) {
        m_[i] = -INFINITY;
        l_[i] = 0.0f;
        accp[i][0] = 0ull;
        accp[i][1] = 0ull;
    }

    const float scale = 0.125f;

    for (int kt = 0; kt <= qt; kt++) {
        __syncthreads();

        const float* kb = qkv + ((size_t)(b * SEQ + kt * 64)) * (3 * DIM) + DIM + h * DH;
        const float* vb = kb + DIM;
#pragma unroll
        for (int rr = 0; rr < 4; rr++) {
            int row = rr * 16 + lr;
            float4 kv = *(const float4*)(kb + (size_t)row * (3 * DIM) + lc4);
            Kt[(lc4 + 0) * PAD + row] = kv.x;
            Kt[(lc4 + 1) * PAD + row] = kv.y;
            Kt[(lc4 + 2) * PAD + row] = kv.z;
            Kt[(lc4 + 3) * PAD + row] = kv.w;
            float4 vv = *(const float4*)(vb + (size_t)row * (3 * DIM) + lc4);
            Vs[row * PAD + lc4 + 0] = vv.x;
            Vs[row * PAD + lc4 + 1] = vv.y;
            Vs[row * PAD + lc4 + 2] = vv.z;
            Vs[row * PAD + lc4 + 3] = vv.w;
        }
        __syncthreads();

        unsigned long long s2[4][2];
#pragma unroll
        for (int i = 0; i < 4; i++) { s2[i][0] = 0ull; s2[i][1] = 0ull; }

#pragma unroll 8
        for (int d = 0; d < 64; d++) {
            unsigned long long kp0 = *(const unsigned long long*)&Kt[d * PAD + (tx << 2)];
            unsigned long long kp1 = *(const unsigned long long*)&Kt[d * PAD + (tx << 2) + 2];
#pragma unroll
            for (int i = 0; i < 4; i++) {
                unsigned long long qd;
                DUP2(qd, Qs[(ty * 4 + i) * PAD + d]);
                FMA2(s2[i][0], qd, kp0);
                FMA2(s2[i][1], qd, kp1);
            }
        }

        float s_[4][4];
#pragma unroll
        for (int i = 0; i < 4; i++) {
            UNPK2(s_[i][0], s_[i][1], s2[i][0]);
            UNPK2(s_[i][2], s_[i][3], s2[i][1]);
        }

#pragma unroll
        for (int i = 0; i < 4; i++) {
            float mx = -INFINITY;
#pragma unroll
            for (int j = 0; j < 4; j++) {
                float sv = s_[i][j] * scale;
                if (kt == qt && ((tx << 2) + j) > (ty * 4 + i)) sv = -INFINITY;
                s_[i][j] = sv;
                mx = fmaxf(mx, sv);
            }
#pragma unroll
            for (int off = 8; off > 0; off >>= 1)
                mx = fmaxf(mx, __shfl_xor_sync(0xffffffffu, mx, off));
            float mn  = fmaxf(m_[i], mx);
            float fac = expf(m_[i] - mn);
            float ps  = 0.0f;
#pragma unroll
            for (int j = 0; j < 4; j++) {
                float p = expf(s_[i][j] - mn);
                s_[i][j] = p;
                ps += p;
            }
#pragma unroll
            for (int off = 8; off > 0; off >>= 1)
                ps += __shfl_xor_sync(0xffffffffu, ps, off);
            m_[i] = mn;
            l_[i] = l_[i] * fac + ps;
            unsigned long long fd;
            DUP2(fd, fac);
            MUL2(accp[i][0], fd);
            MUL2(accp[i][1], fd);
        }

#pragma unroll
        for (int i = 0; i < 4; i++)
#pragma unroll
            for (int j = 0; j < 4; j++)
                Ps[(ty * 4 + i) * PAD + (tx << 2) + j] = s_[i][j];
        __syncthreads();

#pragma unroll 4
        for (int k = 0; k < 64; k++) {
            unsigned long long vp0 = *(const unsigned long long*)&Vs[k * PAD + (tx << 2)];
            unsigned long long vp1 = *(const unsigned long long*)&Vs[k * PAD + (tx << 2) + 2];
#pragma unroll
            for (int i = 0; i < 4; i++) {
                unsigned long long pd;
                DUP2(pd, Ps[(ty * 4 + i) * PAD + k]);
                FMA2(accp[i][0], pd, vp0);
                FMA2(accp[i][1], pd, vp1);
            }
        }
    }

#pragma unroll
    for (int i = 0; i < 4; i++) {
        float inv = 1.0f / l_[i];
        float o0, o1, o2, o3;
        UNPK2(o0, o1, accp[i][0]);
        UNPK2(o2, o3, accp[i][1]);
        int grow = b * SEQ + qt * 64 + ty * 4 + i;
        float4 o = make_float4(o0 * inv, o1 * inv, o2 * inv, o3 * inv);
        *(float4*)&out[(size_t)grow * DIM + h * DH + (tx << 2)] = o;
    }
}

// ---------------------------------------------------------------------------
extern "C" void kernel_launch(void* const* d_in, const int* in_sizes, int n_in,
                              void* d_out, int out_size) {
    const float* x    = nullptr;
    const float* Wqkv = nullptr;
    const float* Wout = nullptr;
    for (int i = 0; i < n_in; i++) {
        if (in_sizes[i] == BATCH * SEQ * DIM)  x    = (const float*)d_in[i];
        else if (in_sizes[i] == 3 * DIM * DIM) Wqkv = (const float*)d_in[i];
        else if (in_sizes[i] == DIM * DIM)     Wout = (const float*)d_in[i];
    }
    float* out = (float*)d_out;

    float *qkv, *att;
    __nv_bfloat16 *xh, *xl, *wqh, *wql, *woh, *wol, *ath, *atl;
    cudaGetSymbolAddress((void**)&qkv, g_qkv);
    cudaGetSymbolAddress((void**)&att, g_att);
    cudaGetSymbolAddress((void**)&xh,  g_xh);
    cudaGetSymbolAddress((void**)&xl,  g_xl);
    cudaGetSymbolAddress((void**)&wqh, g_wqh);
    cudaGetSymbolAddress((void**)&wql, g_wql);
    cudaGetSymbolAddress((void**)&woh, g_woh);
    cudaGetSymbolAddress((void**)&wol, g_wol);
    cudaGetSymbolAddress((void**)&ath, g_ath);
    cudaGetSymbolAddress((void**)&atl, g_atl);

    const int M = BATCH * SEQ;  // 4096

    cudaFuncSetAttribute(bf16gemm, cudaFuncAttributeMaxDynamicSharedMemorySize, GEMM_SMEM);

    // 0) Pre-split inputs to bf16 hi/lo planes (weights transposed)
    split_bf16<<<(M * DIM / 4) / 256, 256>>>(x, xh, xl, M * DIM / 4);
    split_wt<<<dim3(3 * DIM / 32, DIM / 32), dim3(32, 8)>>>(Wqkv, wqh, wql, DIM, 3 * DIM);
    split_wt<<<dim3(DIM / 32, DIM / 32), dim3(32, 8)>>>(Wout, woh, wol, DIM, DIM);

    // 1) QKV projection
    bf16gemm<<<dim3(3 * DIM / 128, M / 128), 256, GEMM_SMEM>>>(xh, xl, wqh, wql, qkv, M, 3 * DIM, DIM);

    // 2) RoPE (interleaved, -theta)
    rope_kernel<<<(BATCH * SEQ * 2 * NH * 16) / 256, 256>>>(qkv);

    // 3) Causal flash attention -> att
    int smem = 4 * 64 * PAD * (int)sizeof(float);
    cudaFuncSetAttribute(attn_kernel, cudaFuncAttributeMaxDynamicSharedMemorySize, smem);
    attn_kernel<<<dim3(SEQ / 64, NH, BATCH), 256, smem>>>(qkv, att);

    // 3b) Split attention output
    split_bf16<<<(M * DIM / 4) / 256, 256>>>(att, ath, atl, M * DIM / 4);

    // 4) Output projection
    bf16gemm<<<dim3(DIM / 128, M / 128), 256, GEMM_SMEM>>>(ath, atl, woh, wol, out, M, DIM, DIM);
}